// round 1
// baseline (speedup 1.0000x reference)
#include <cuda_runtime.h>
#include <cuda_fp8.h>
#include <cuda_fp16.h>
#include <math_constants.h>

// Problem shape (fixed by the dataset): B=1, H=16, S=4096, D=64
#define SQ 4096
#define HD 64
#define NH 16
#define BM 64
#define BN 64
#define LDP 68   // padded stride (floats) for the K/P shared tile

// fp8-dequantized (fp32) scratch copies of Q (pre-scaled by sm_scale), K, V
__device__ float g_qd[NH * SQ * HD];
__device__ float g_kd[NH * SQ * HD];
__device__ float g_vd[NH * SQ * HD];

// e4m3 quantize round-trip: saturate + RN-even, exactly like
// jnp.clip(x,-448,448).astype(float8_e4m3fn).astype(float32)
__device__ __forceinline__ float fp8_rt(float x) {
    __nv_fp8_storage_t b = __nv_cvt_float_to_fp8(x, __NV_SATFINITE, __NV_E4M3);
    __half_raw hr = __nv_cvt_fp8_to_halfraw(b, __NV_E4M3);
    return __half2float(*reinterpret_cast<const __half*>(&hr));
}

// Quantize-dequantize a tensor into fp32 scratch.
// out = fp8(x / scale) * (scale * post_mul); post_mul=0.125 (exact pow2) folds
// sm_scale into Q.
__global__ void quant_kernel(const float4* __restrict__ in,
                             float4* __restrict__ outp,
                             const float* __restrict__ scale_p,
                             float post_mul, int n4) {
    int i = blockIdx.x * blockDim.x + threadIdx.x;
    if (i >= n4) return;
    float s = *scale_p;
    float inv = 1.0f / s;
    float m = s * post_mul;
    float4 v = in[i];
    v.x = fp8_rt(v.x * inv) * m;
    v.y = fp8_rt(v.y * inv) * m;
    v.z = fp8_rt(v.z * inv) * m;
    v.w = fp8_rt(v.w * inv) * m;
    outp[i] = v;
}

// Flash attention, 2 sweeps over K tiles:
//   sweep 1: scores -> online (m, l) per query row
//   sweep 2: recompute scores, p = fp8_rt(exp(s-m)/l / dsc)*dsc, O += p*V
// Block: 256 threads = 16(tx) x 16(ty); thread owns a 4x4 micro-tile.
__global__ __launch_bounds__(256) void attn_kernel(
    const float* __restrict__ dsc_p,   // descale_amax
    const float* __restrict__ osc_p,   // out_scale
    float* __restrict__ out) {
    extern __shared__ float sm[];
    float* q_s  = sm;                  // [HD][BM]  transposed Q tile
    float* kp_s = sm + HD * BM;        // [HD][LDP] transposed K tile / P tile
    float* v_s  = kp_s + HD * LDP;     // [BN][HD]  natural V tile

    const int h  = blockIdx.y;
    const int s0 = blockIdx.x * BM;
    const int tid = threadIdx.x;
    const int tx = tid & 15;
    const int ty = tid >> 4;

    const float* Qh = g_qd + (size_t)h * SQ * HD;
    const float* Kh = g_kd + (size_t)h * SQ * HD;
    const float* Vh = g_vd + (size_t)h * SQ * HD;

    // Load Q tile transposed: q_s[d][row]
#pragma unroll
    for (int e = 0; e < 16; e++) {
        int lin = tid + e * 256;
        int row = lin >> 6, d = lin & 63;
        q_s[d * BM + row] = Qh[(s0 + row) * HD + d];
    }

    float m0[4], l0[4];
#pragma unroll
    for (int r = 0; r < 4; r++) { m0[r] = -CUDART_INF_F; l0[r] = 0.0f; }

    __syncthreads();

    // ---------------- PASS 1: row max + row sum ----------------
    for (int t = 0; t < SQ / BN; t++) {
        const int n0 = t * BN;
#pragma unroll
        for (int e = 0; e < 16; e++) {
            int lin = tid + e * 256;
            int j = lin >> 6, d = lin & 63;
            kp_s[d * LDP + j] = Kh[(n0 + j) * HD + d];
        }
        __syncthreads();

        float acc[16];
#pragma unroll
        for (int i = 0; i < 16; i++) acc[i] = 0.0f;
#pragma unroll 8
        for (int kk = 0; kk < HD; kk++) {
            float4 a4 = *(const float4*)&q_s[kk * BM + ty * 4];
            float4 b4 = *(const float4*)&kp_s[kk * LDP + tx * 4];
            float ar[4] = {a4.x, a4.y, a4.z, a4.w};
            float br[4] = {b4.x, b4.y, b4.z, b4.w};
#pragma unroll
            for (int r = 0; r < 4; r++)
#pragma unroll
                for (int c = 0; c < 4; c++)
                    acc[r * 4 + c] = fmaf(ar[r], br[c], acc[r * 4 + c]);
        }

        // Online softmax stats; same-row threads are 16 contiguous lanes.
#pragma unroll
        for (int r = 0; r < 4; r++) {
            float mx = fmaxf(fmaxf(acc[r * 4 + 0], acc[r * 4 + 1]),
                             fmaxf(acc[r * 4 + 2], acc[r * 4 + 3]));
#pragma unroll
            for (int w = 8; w >= 1; w >>= 1)
                mx = fmaxf(mx, __shfl_xor_sync(0xffffffffu, mx, w));
            float mn = fmaxf(m0[r], mx);
            float ssum = __expf(acc[r * 4 + 0] - mn) + __expf(acc[r * 4 + 1] - mn)
                       + __expf(acc[r * 4 + 2] - mn) + __expf(acc[r * 4 + 3] - mn);
#pragma unroll
            for (int w = 8; w >= 1; w >>= 1)
                ssum += __shfl_xor_sync(0xffffffffu, ssum, w);
            l0[r] = l0[r] * __expf(m0[r] - mn) + ssum;
            m0[r] = mn;
        }
        __syncthreads();
    }

    const float dsc = *dsc_p;
    const float inv_ds = 1.0f / dsc;
    const float osc = *osc_p;
    float il[4];
#pragma unroll
    for (int r = 0; r < 4; r++) il[r] = 1.0f / l0[r];

    float o[16];
#pragma unroll
    for (int i = 0; i < 16; i++) o[i] = 0.0f;

    // ---------------- PASS 2: quantized probs + PV ----------------
    for (int t = 0; t < SQ / BN; t++) {
        const int n0 = t * BN;
#pragma unroll
        for (int e = 0; e < 16; e++) {
            int lin = tid + e * 256;
            int j = lin >> 6, d = lin & 63;
            kp_s[d * LDP + j] = Kh[(n0 + j) * HD + d];
            v_s[lin] = Vh[n0 * HD + lin];
        }
        __syncthreads();

        float acc[16];
#pragma unroll
        for (int i = 0; i < 16; i++) acc[i] = 0.0f;
#pragma unroll 8
        for (int kk = 0; kk < HD; kk++) {
            float4 a4 = *(const float4*)&q_s[kk * BM + ty * 4];
            float4 b4 = *(const float4*)&kp_s[kk * LDP + tx * 4];
            float ar[4] = {a4.x, a4.y, a4.z, a4.w};
            float br[4] = {b4.x, b4.y, b4.z, b4.w};
#pragma unroll
            for (int r = 0; r < 4; r++)
#pragma unroll
                for (int c = 0; c < 4; c++)
                    acc[r * 4 + c] = fmaf(ar[r], br[c], acc[r * 4 + c]);
        }
        __syncthreads();  // everyone done reading kp_s as K

        // Quantized probabilities -> kp_s reused as p_s[key][row]
#pragma unroll
        for (int r = 0; r < 4; r++) {
#pragma unroll
            for (int c = 0; c < 4; c++) {
                float p = __expf(acc[r * 4 + c] - m0[r]) * il[r];
                float pd = fp8_rt(p * inv_ds) * dsc;
                kp_s[(tx * 4 + c) * LDP + ty * 4 + r] = pd;
            }
        }
        __syncthreads();

#pragma unroll 8
        for (int kk = 0; kk < BN; kk++) {
            float4 a4 = *(const float4*)&kp_s[kk * LDP + ty * 4];
            float4 b4 = *(const float4*)&v_s[kk * HD + tx * 4];
            float ar[4] = {a4.x, a4.y, a4.z, a4.w};
            float br[4] = {b4.x, b4.y, b4.z, b4.w};
#pragma unroll
            for (int r = 0; r < 4; r++)
#pragma unroll
                for (int c = 0; c < 4; c++)
                    o[r * 4 + c] = fmaf(ar[r], br[c], o[r * 4 + c]);
        }
        __syncthreads();
    }

    // Epilogue: output fp8 quantize-dequant, fp32 store
#pragma unroll
    for (int r = 0; r < 4; r++) {
        float4 res;
        res.x = fp8_rt(o[r * 4 + 0] / osc) * osc;
        res.y = fp8_rt(o[r * 4 + 1] / osc) * osc;
        res.z = fp8_rt(o[r * 4 + 2] / osc) * osc;
        res.w = fp8_rt(o[r * 4 + 3] / osc) * osc;
        size_t row = (size_t)h * SQ + s0 + ty * 4 + r;
        *(float4*)&out[row * HD + tx * 4] = res;
    }
}

extern "C" void kernel_launch(void* const* d_in, const int* in_sizes, int n_in,
                              void* d_out, int out_size) {
    const float* q = (const float*)d_in[0];
    const float* k = (const float*)d_in[1];
    const float* v = (const float*)d_in[2];
    const float* scale_q = (const float*)d_in[3];
    const float* scale_k = (const float*)d_in[4];
    const float* scale_v = (const float*)d_in[5];
    const float* descale_amax = (const float*)d_in[6];
    const float* out_scale = (const float*)d_in[7];
    float* out = (float*)d_out;

    void *qd, *kd, *vd;
    cudaGetSymbolAddress(&qd, g_qd);
    cudaGetSymbolAddress(&kd, g_kd);
    cudaGetSymbolAddress(&vd, g_vd);

    const int n4 = NH * SQ * HD / 4;
    const int qblocks = (n4 + 255) / 256;
    quant_kernel<<<qblocks, 256>>>((const float4*)q, (float4*)qd, scale_q, 0.125f, n4);
    quant_kernel<<<qblocks, 256>>>((const float4*)k, (float4*)kd, scale_k, 1.0f, n4);
    quant_kernel<<<qblocks, 256>>>((const float4*)v, (float4*)vd, scale_v, 1.0f, n4);

    const size_t smem = (size_t)(HD * BM + HD * LDP + BN * HD) * sizeof(float);  // 50176 B
    cudaFuncSetAttribute(attn_kernel, cudaFuncAttributeMaxDynamicSharedMemorySize,
                         (int)smem);
    dim3 grid(SQ / BM, NH);
    attn_kernel<<<grid, 256, smem>>>(descale_amax, out_scale, out);
}